// round 1
// baseline (speedup 1.0000x reference)
#include <cuda_runtime.h>
#include <cuda_bf16.h>

// ---------------------------------------------------------------------------
// Compile-time normalization constants K(l,m):
//   K = sqrt((2l+1)/(4pi) * (l-m)!/(l+m)!),   times sqrt(2) for m != 0
// ---------------------------------------------------------------------------
namespace {

constexpr double csqrt(double x) {
    double g = x > 1.0 ? x : 1.0;
    for (int i = 0; i < 100; i++) g = 0.5 * (g + x / g);
    return g;
}
constexpr double dfact(int n) {
    double r = 1.0;
    for (int i = 2; i <= n; i++) r *= (double)i;
    return r;
}
constexpr double PI_D = 3.14159265358979323846;

struct KTab { float c[8][8]; };

constexpr KTab mk_ktab() {
    KTab t{};
    for (int l = 0; l < 8; l++)
        for (int m = 0; m <= l; m++) {
            double K = csqrt((2.0 * l + 1.0) / (4.0 * PI_D)
                             * dfact(l - m) / dfact(l + m));
            if (m > 0) K *= csqrt(2.0);
            t.c[l][m] = (float)K;
        }
    return t;
}

} // namespace

__constant__ KTab g_K = mk_ktab();

// ---------------------------------------------------------------------------
// Kernel: one thread computes one point's 64 SH values into SMEM (transposed),
// then the block writes each per-l output region with fully coalesced stores.
// ---------------------------------------------------------------------------
constexpr int TPB  = 128;
constexpr int NCOL = 64;   // sum_{l=0..7} (2l+1) = 64

__global__ __launch_bounds__(TPB)
void sph_harm_kernel(const float* __restrict__ cos_theta,
                     const float* __restrict__ phi,
                     float* __restrict__ out,
                     int N)
{
    __shared__ float sm[NCOL][TPB + 1];   // +1 pad: conflict-free gather

    const int t  = threadIdx.x;
    const long long bs = (long long)blockIdx.x * TPB;
    const int n  = (int)bs + t;

    if (n < N) {
        const float x = cos_theta[n];
        const float p = phi[n];
        const float s = sqrtf(fmaxf(1.0f - x * x, 0.0f));

        float sp, cp;
        __sincosf(p, &sp, &cp);

        float pmm = 1.0f;                 // P_m^m
        float cm = 1.0f, smv = 0.0f;      // cos(m*phi), sin(m*phi)

        #pragma unroll
        for (int m = 0; m <= 7; m++) {
            if (m > 0) {
                pmm = (-(2.0f * m - 1.0f)) * s * pmm;     // Condon-Shortley
                const float cn = cp * cm - sp * smv;       // angle addition
                const float sn = sp * cm + cp * smv;
                cm = cn; smv = sn;
            }

            // l = m
            {
                const int l = m;
                if (m == 0) {
                    sm[l * l + l][t] = g_K.c[l][0] * pmm;
                } else {
                    const float kp = g_K.c[l][m] * pmm;
                    sm[l * l + l - m][t] = kp * smv;
                    sm[l * l + l + m][t] = kp * cm;
                }
            }

            if (m < 7) {
                // l = m+1 :  P_{m+1}^m = (2m+1) x P_m^m
                float plm1 = (2.0f * m + 1.0f) * x * pmm;
                {
                    const int l = m + 1;
                    if (m == 0) {
                        sm[l * l + l][t] = g_K.c[l][0] * plm1;
                    } else {
                        const float kp = g_K.c[l][m] * plm1;
                        sm[l * l + l - m][t] = kp * smv;
                        sm[l * l + l + m][t] = kp * cm;
                    }
                }
                float pl2 = pmm;   // P_{l-2}^m
                #pragma unroll
                for (int l = m + 2; l <= 7; l++) {
                    // (l-m) P_l^m = (2l-1) x P_{l-1}^m - (l+m-1) P_{l-2}^m
                    const float plc =
                        ((2.0f * l - 1.0f) * x * plm1 - (float)(l + m - 1) * pl2)
                        * (1.0f / (float)(l - m));
                    pl2 = plm1; plm1 = plc;
                    if (m == 0) {
                        sm[l * l + l][t] = g_K.c[l][0] * plc;
                    } else {
                        const float kp = g_K.c[l][m] * plc;
                        sm[l * l + l - m][t] = kp * smv;
                        sm[l * l + l + m][t] = kp * cm;
                    }
                }
            }
        }
    }

    __syncthreads();

    // ------------------------------------------------------------------
    // Coalesced write-out: array l occupies out[N*l*l ...], row-major
    // [N, 2l+1]; this block owns the contiguous slice of `rows` rows.
    // ------------------------------------------------------------------
    const int rows = (int)min((long long)TPB, (long long)N - bs);

    #pragma unroll
    for (int l = 0; l <= 7; l++) {
        const int w = 2 * l + 1;
        float* dst = out + (size_t)N * (size_t)(l * l) + (size_t)bs * (size_t)w;
        const int cnt = rows * w;
        for (int i = t; i < cnt; i += TPB) {
            const int pt = i / w;            // w is a compile-time constant here
            const int j  = i - pt * w;
            dst[i] = sm[l * l + j][pt];
        }
    }
}

extern "C" void kernel_launch(void* const* d_in, const int* in_sizes, int n_in,
                              void* d_out, int out_size)
{
    const float* cos_theta = (const float*)d_in[0];
    const float* phi       = (const float*)d_in[1];
    float* out             = (float*)d_out;
    const int N = in_sizes[0];

    const int blocks = (N + TPB - 1) / TPB;
    sph_harm_kernel<<<blocks, TPB>>>(cos_theta, phi, out, N);
}

// round 2
// speedup vs baseline: 1.2021x; 1.2021x over previous
#include <cuda_runtime.h>
#include <cuda_bf16.h>

// ---------------------------------------------------------------------------
// Compile-time normalization constants K(l,m):
//   K = sqrt((2l+1)/(4pi) * (l-m)!/(l+m)!),   times sqrt(2) for m != 0
// ---------------------------------------------------------------------------
namespace {

constexpr double csqrt(double x) {
    double g = x > 1.0 ? x : 1.0;
    for (int i = 0; i < 100; i++) g = 0.5 * (g + x / g);
    return g;
}
constexpr double dfact(int n) {
    double r = 1.0;
    for (int i = 2; i <= n; i++) r *= (double)i;
    return r;
}
constexpr double PI_D = 3.14159265358979323846;

struct KTab { float c[8][8]; };

constexpr KTab mk_ktab() {
    KTab t{};
    for (int l = 0; l < 8; l++)
        for (int m = 0; m <= l; m++) {
            double K = csqrt((2.0 * l + 1.0) / (4.0 * PI_D)
                             * dfact(l - m) / dfact(l + m));
            if (m > 0) K *= csqrt(2.0);
            t.c[l][m] = (float)K;
        }
    return t;
}

} // namespace

__constant__ KTab g_K = mk_ktab();

// ---------------------------------------------------------------------------
// Kernel. SMEM staging buffer is laid out IDENTICALLY to the output:
//   region l at smem offset 128*l*l, element (pt, j) at  + pt*(2l+1) + j.
// Compute phase: thread t stores its point's values at t*w + j.
//   For fixed j, lane banks are (t*w + j) mod 32; w odd => permutation of
//   banks => conflict-free STS.
// Write phase: smem address == output index => straight sequential
//   LDS.128 + STG.128, conflict-free, no div/mod.
// l = 0 (w = 1) is written directly to global (already coalesced).
// ---------------------------------------------------------------------------
constexpr int TPB = 128;

__global__ __launch_bounds__(TPB)
void sph_harm_kernel(const float* __restrict__ cos_theta,
                     const float* __restrict__ phi,
                     float* __restrict__ out,
                     int N)
{
    // regions l=1..7: sum 128*(2l+1) = 128*63 floats = 31.5 KB
    __shared__ float sm[128 * 63];

    const int t  = threadIdx.x;
    const long long bs = (long long)blockIdx.x * TPB;
    const int n  = (int)bs + t;

    if (n < N) {
        const float x = cos_theta[n];
        const float p = phi[n];
        const float s = sqrtf(fmaxf(1.0f - x * x, 0.0f));

        float sp, cp;
        __sincosf(p, &sp, &cp);

        float pmm = 1.0f;                 // P_m^m
        float cm = 1.0f, smv = 0.0f;      // cos(m*phi), sin(m*phi)

        #pragma unroll
        for (int m = 0; m <= 7; m++) {
            if (m > 0) {
                pmm = (-(2.0f * m - 1.0f)) * s * pmm;     // Condon-Shortley
                const float cn = cp * cm - sp * smv;       // angle addition
                const float sn = sp * cm + cp * smv;
                cm = cn; smv = sn;
            }

            // ---- l = m ----
            {
                constexpr int dummy = 0; (void)dummy;
                const int l = m;
                if (m == 0) {
                    // l=0: direct coalesced global store
                    out[n] = g_K.c[0][0] * pmm;
                } else {
                    const int w    = 2 * l + 1;
                    const int base = 128 * (l * l - 1) + t * w; // -1: l=0 skipped
                    const float kp = g_K.c[l][m] * pmm;
                    sm[base + (l - m)] = kp * smv;
                    sm[base + (l + m)] = kp * cm;
                }
            }

            if (m < 7) {
                // l = m+1 :  P_{m+1}^m = (2m+1) x P_m^m
                float plm1 = (2.0f * m + 1.0f) * x * pmm;
                {
                    const int l    = m + 1;
                    const int w    = 2 * l + 1;
                    const int base = 128 * (l * l - 1) + t * w;
                    if (m == 0) {
                        sm[base + l] = g_K.c[l][0] * plm1;
                    } else {
                        const float kp = g_K.c[l][m] * plm1;
                        sm[base + (l - m)] = kp * smv;
                        sm[base + (l + m)] = kp * cm;
                    }
                }
                float pl2 = pmm;   // P_{l-2}^m
                #pragma unroll
                for (int l = m + 2; l <= 7; l++) {
                    // (l-m) P_l^m = (2l-1) x P_{l-1}^m - (l+m-1) P_{l-2}^m
                    const float plc =
                        ((2.0f * l - 1.0f) * x * plm1 - (float)(l + m - 1) * pl2)
                        * (1.0f / (float)(l - m));
                    pl2 = plm1; plm1 = plc;
                    const int w    = 2 * l + 1;
                    const int base = 128 * (l * l - 1) + t * w;
                    if (m == 0) {
                        sm[base + l] = g_K.c[l][0] * plc;
                    } else {
                        const float kp = g_K.c[l][m] * plc;
                        sm[base + (l - m)] = kp * smv;
                        sm[base + (l + m)] = kp * cm;
                    }
                }
            }
        }
    }

    __syncthreads();

    // ------------------------------------------------------------------
    // Write-out. smem layout == output layout, so this is a pure
    // sequential copy per region: LDS.128 + STG.128, conflict-free.
    // ------------------------------------------------------------------
    const int rows = (int)min((long long)TPB, (long long)N - bs);

    if (rows == TPB) {
        #pragma unroll
        for (int l = 1; l <= 7; l++) {
            const int w = 2 * l + 1;
            const float4* src = (const float4*)(sm + 128 * (l * l - 1));
            float4* dst = (float4*)(out + (size_t)N * (size_t)(l * l)
                                        + (size_t)bs * (size_t)w);
            const int cnt4 = (TPB * w) / 4;     // 32*w, compile-time
            #pragma unroll
            for (int i = t; i < cnt4; i += TPB)
                dst[i] = src[i];
        }
    } else {
        // tail block (not hit for N = 2M, kept for generality)
        #pragma unroll
        for (int l = 1; l <= 7; l++) {
            const int w = 2 * l + 1;
            const float* src = sm + 128 * (l * l - 1);
            float* dst = out + (size_t)N * (size_t)(l * l)
                             + (size_t)bs * (size_t)w;
            const int cnt = rows * w;
            for (int i = t; i < cnt; i += TPB)
                dst[i] = src[i];
        }
    }
}

extern "C" void kernel_launch(void* const* d_in, const int* in_sizes, int n_in,
                              void* d_out, int out_size)
{
    const float* cos_theta = (const float*)d_in[0];
    const float* phi       = (const float*)d_in[1];
    float* out             = (float*)d_out;
    const int N = in_sizes[0];

    const int blocks = (N + TPB - 1) / TPB;
    sph_harm_kernel<<<blocks, TPB>>>(cos_theta, phi, out, N);
}

// round 3
// speedup vs baseline: 1.2184x; 1.0135x over previous
#include <cuda_runtime.h>
#include <cuda_bf16.h>
#include <cstdint>

// ---------------------------------------------------------------------------
// Compile-time normalization constants K(l,m):
//   K = sqrt((2l+1)/(4pi) * (l-m)!/(l+m)!),   times sqrt(2) for m != 0
// ---------------------------------------------------------------------------
namespace {

constexpr double csqrt(double x) {
    double g = x > 1.0 ? x : 1.0;
    for (int i = 0; i < 100; i++) g = 0.5 * (g + x / g);
    return g;
}
constexpr double dfact(int n) {
    double r = 1.0;
    for (int i = 2; i <= n; i++) r *= (double)i;
    return r;
}
constexpr double PI_D = 3.14159265358979323846;

struct KTab { float c[8][8]; };

constexpr KTab mk_ktab() {
    KTab t{};
    for (int l = 0; l < 8; l++)
        for (int m = 0; m <= l; m++) {
            double K = csqrt((2.0 * l + 1.0) / (4.0 * PI_D)
                             * dfact(l - m) / dfact(l + m));
            if (m > 0) K *= csqrt(2.0);
            t.c[l][m] = (float)K;
        }
    return t;
}

} // namespace

__constant__ KTab g_K = mk_ktab();

// ---------------------------------------------------------------------------
// SMEM staging buffer laid out IDENTICALLY to the output:
//   region l (l=1..7) at smem float offset 128*(l*l-1),
//   element (pt, j) at + pt*(2l+1) + j.
// Compute phase: STS with lane stride w (odd => conflict-free bank perm).
// Write phase: ONE elected thread issues 7 cp.async.bulk shared->global
//   copies (regions are contiguous and 16B-aligned on both sides).
// l = 0 (w = 1) is stored directly to global (already coalesced).
// ---------------------------------------------------------------------------
constexpr int TPB = 128;

__device__ __forceinline__ uint32_t smem_u32(const void* p) {
    uint32_t a;
    asm("{ .reg .u64 t; cvta.to.shared.u64 t, %1; cvt.u32.u64 %0, t; }"
        : "=r"(a) : "l"(p));
    return a;
}

__global__ __launch_bounds__(TPB)
void sph_harm_kernel(const float* __restrict__ cos_theta,
                     const float* __restrict__ phi,
                     float* __restrict__ out,
                     int N)
{
    __shared__ float sm[128 * 63];   // 31.5 KB

    const int t  = threadIdx.x;
    const long long bs = (long long)blockIdx.x * TPB;
    const int n  = (int)bs + t;

    if (n < N) {
        const float x = cos_theta[n];
        const float p = phi[n];
        const float s = sqrtf(fmaxf(1.0f - x * x, 0.0f));

        float sp, cp;
        __sincosf(p, &sp, &cp);

        float pmm = 1.0f;                 // P_m^m
        float cm = 1.0f, smv = 0.0f;      // cos(m*phi), sin(m*phi)

        #pragma unroll
        for (int m = 0; m <= 7; m++) {
            if (m > 0) {
                pmm = (-(2.0f * m - 1.0f)) * s * pmm;     // Condon-Shortley
                const float cn = cp * cm - sp * smv;       // angle addition
                const float sn = sp * cm + cp * smv;
                cm = cn; smv = sn;
            }

            // ---- l = m ----
            {
                const int l = m;
                if (m == 0) {
                    out[n] = g_K.c[0][0] * pmm;            // l=0 direct
                } else {
                    const int w    = 2 * l + 1;
                    const int base = 128 * (l * l - 1) + t * w;
                    const float kp = g_K.c[l][m] * pmm;
                    sm[base + (l - m)] = kp * smv;
                    sm[base + (l + m)] = kp * cm;
                }
            }

            if (m < 7) {
                // l = m+1 :  P_{m+1}^m = (2m+1) x P_m^m
                float plm1 = (2.0f * m + 1.0f) * x * pmm;
                {
                    const int l    = m + 1;
                    const int w    = 2 * l + 1;
                    const int base = 128 * (l * l - 1) + t * w;
                    if (m == 0) {
                        sm[base + l] = g_K.c[l][0] * plm1;
                    } else {
                        const float kp = g_K.c[l][m] * plm1;
                        sm[base + (l - m)] = kp * smv;
                        sm[base + (l + m)] = kp * cm;
                    }
                }
                float pl2 = pmm;   // P_{l-2}^m
                #pragma unroll
                for (int l = m + 2; l <= 7; l++) {
                    // (l-m) P_l^m = (2l-1) x P_{l-1}^m - (l+m-1) P_{l-2}^m
                    const float plc =
                        ((2.0f * l - 1.0f) * x * plm1 - (float)(l + m - 1) * pl2)
                        * (1.0f / (float)(l - m));
                    pl2 = plm1; plm1 = plc;
                    const int w    = 2 * l + 1;
                    const int base = 128 * (l * l - 1) + t * w;
                    if (m == 0) {
                        sm[base + l] = g_K.c[l][0] * plc;
                    } else {
                        const float kp = g_K.c[l][m] * plc;
                        sm[base + (l - m)] = kp * smv;
                        sm[base + (l + m)] = kp * cm;
                    }
                }
            }
        }
    }

    __syncthreads();

    const int rows = (int)min((long long)TPB, (long long)N - bs);

    if (rows == TPB && ((N & 3) == 0)) {
        // --------------------------------------------------------------
        // Bulk async copy: one thread issues 7 shared->global copies.
        // Region l: 512*w bytes, both sides 16B-aligned (N % 4 == 0).
        // --------------------------------------------------------------
        if (t == 0) {
            asm volatile("fence.proxy.async.shared::cta;" ::: "memory");
            #pragma unroll
            for (int l = 1; l <= 7; l++) {
                const int w = 2 * l + 1;
                const uint32_t src = smem_u32(sm + 128 * (l * l - 1));
                float* dstp = out + (size_t)N * (size_t)(l * l)
                                  + (size_t)bs * (size_t)w;
                const uint32_t bytes = (uint32_t)(TPB * w * 4);
                asm volatile(
                    "cp.async.bulk.global.shared::cta.bulk_group [%0], [%1], %2;"
                    :: "l"(dstp), "r"(src), "r"(bytes) : "memory");
            }
            asm volatile("cp.async.bulk.commit_group;" ::: "memory");
            asm volatile("cp.async.bulk.wait_group 0;" ::: "memory");
        }
    } else {
        // tail / unaligned fallback (not hit for N = 2M)
        #pragma unroll
        for (int l = 1; l <= 7; l++) {
            const int w = 2 * l + 1;
            const float* src = sm + 128 * (l * l - 1);
            float* dst = out + (size_t)N * (size_t)(l * l)
                             + (size_t)bs * (size_t)w;
            const int cnt = rows * w;
            for (int i = t; i < cnt; i += TPB)
                dst[i] = src[i];
        }
    }
}

extern "C" void kernel_launch(void* const* d_in, const int* in_sizes, int n_in,
                              void* d_out, int out_size)
{
    const float* cos_theta = (const float*)d_in[0];
    const float* phi       = (const float*)d_in[1];
    float* out             = (float*)d_out;
    const int N = in_sizes[0];

    const int blocks = (N + TPB - 1) / TPB;
    sph_harm_kernel<<<blocks, TPB>>>(cos_theta, phi, out, N);
}

// round 5
// speedup vs baseline: 1.2264x; 1.0066x over previous
#include <cuda_runtime.h>
#include <cuda_bf16.h>
#include <cstdint>

// ---------------------------------------------------------------------------
// Compile-time normalization constants K(l,m) baked in as immediates:
//   K = sqrt((2l+1)/(4pi) * (l-m)!/(l+m)!),   times sqrt(2) for m != 0
// ---------------------------------------------------------------------------
namespace {

constexpr double csqrt(double x) {
    double g = x > 1.0 ? x : 1.0;
    for (int i = 0; i < 100; i++) g = 0.5 * (g + x / g);
    return g;
}
constexpr double dfact(int n) {
    double r = 1.0;
    for (int i = 2; i <= n; i++) r *= (double)i;
    return r;
}
constexpr double PI_D = 3.14159265358979323846;

struct KTab { float c[8][8]; };

constexpr KTab mk_ktab() {
    KTab t{};
    for (int l = 0; l < 8; l++)
        for (int m = 0; m <= l; m++) {
            double K = csqrt((2.0 * l + 1.0) / (4.0 * PI_D)
                             * dfact(l - m) / dfact(l + m));
            if (m > 0) K *= csqrt(2.0);
            t.c[l][m] = (float)K;
        }
    return t;
}

// __device__ constexpr: usable in device code; after full unroll every
// access has constant indices -> folded to FP immediates in SASS.
__device__ constexpr KTab g_Kc = mk_ktab();

} // namespace

// ---------------------------------------------------------------------------
// l-outer pipelined kernel.
// SMEM staging buffer laid out IDENTICALLY to the output:
//   region l (l=1..7) at smem float offset 128*(l*l-1),
//   element (pt, j) at + pt*(2l+1) + j.
// After region l is written (barrier), one thread issues its
// cp.async.bulk shared->global copy and everyone continues with l+1:
// the copy overlaps the remaining compute, smoothing DRAM traffic.
// l = 0 is the constant Y00 (coalesced direct store).
// ---------------------------------------------------------------------------
constexpr int TPB = 128;

__device__ __forceinline__ uint32_t smem_u32(const void* p) {
    uint32_t a;
    asm("{ .reg .u64 t; cvta.to.shared.u64 t, %1; cvt.u32.u64 %0, t; }"
        : "=r"(a) : "l"(p));
    return a;
}

__global__ __launch_bounds__(TPB)
void sph_harm_kernel(const float* __restrict__ cos_theta,
                     const float* __restrict__ phi,
                     float* __restrict__ out,
                     int N)
{
    __shared__ float smb[128 * 63];   // 31.5 KB, == output layout

    const int t  = threadIdx.x;
    const long long bs = (long long)blockIdx.x * TPB;
    const int n   = (int)bs + t;
    const int rows = (int)min((long long)TPB, (long long)N - bs);
    const bool full = (rows == TPB) && ((N & 3) == 0);

    // Clamped index so tail blocks can run the same (barrier-laden) path.
    const int nc = (n < N) ? n : (N - 1);

    const float x = cos_theta[nc];
    const float p = phi[nc];
    const float s = sqrtf(fmaxf(1.0f - x * x, 0.0f));

    float sp, cp;
    __sincosf(p, &sp, &cp);

    // l = 0 : Y00 is a constant.
    if (n < N) out[n] = g_Kc.c[0][0];

    // Register state for the upward-l recurrences (all indices constant
    // after full unroll -> promoted to registers).
    float Pp[8];    // P_{l-1}^m
    float Ppp[8];   // P_{l-2}^m
    float cmv[8], smv[8];
    Pp[0] = 1.0f;             // P_0^0
    cmv[0] = 1.0f; smv[0] = 0.0f;

    #pragma unroll
    for (int l = 1; l <= 7; l++) {
        float Pl[8];
        // (l-m) P_l^m = (2l-1) x P_{l-1}^m - (l+m-1) P_{l-2}^m
        #pragma unroll
        for (int m = 0; m <= l - 2; m++)
            Pl[m] = ((2.0f * l - 1.0f) * x * Pp[m]
                     - (float)(l + m - 1) * Ppp[m]) * (1.0f / (float)(l - m));
        // P_l^{l-1} = (2l-1) x P_{l-1}^{l-1}
        Pl[l - 1] = (2.0f * l - 1.0f) * x * Pp[l - 1];
        // P_l^l = -(2l-1) s P_{l-1}^{l-1}   (Condon-Shortley)
        Pl[l]     = -(2.0f * l - 1.0f) * s * Pp[l - 1];

        // extend trig recurrences to m = l
        cmv[l] = cp * cmv[l - 1] - sp * smv[l - 1];
        smv[l] = sp * cmv[l - 1] + cp * smv[l - 1];

        // emit region l into smem (lane stride w odd -> conflict-free)
        {
            const int w    = 2 * l + 1;
            const int base = 128 * (l * l - 1) + t * w;
            smb[base + l] = g_Kc.c[l][0] * Pl[0];
            #pragma unroll
            for (int m = 1; m <= l; m++) {
                const float kp = g_Kc.c[l][m] * Pl[m];
                smb[base + (l - m)] = kp * smv[m];
                smb[base + (l + m)] = kp * cmv[m];
            }
        }

        __syncthreads();

        if (full && t == 0) {
            asm volatile("fence.proxy.async.shared::cta;" ::: "memory");
            const int w = 2 * l + 1;
            const uint32_t src = smem_u32(smb + 128 * (l * l - 1));
            float* dstp = out + (size_t)N * (size_t)(l * l)
                              + (size_t)bs * (size_t)w;
            const uint32_t bytes = (uint32_t)(TPB * w * 4);
            asm volatile(
                "cp.async.bulk.global.shared::cta.bulk_group [%0], [%1], %2;"
                :: "l"(dstp), "r"(src), "r"(bytes) : "memory");
            asm volatile("cp.async.bulk.commit_group;" ::: "memory");
        }

        // shift state for next l
        #pragma unroll
        for (int m = 0; m <= l - 1; m++) Ppp[m] = Pp[m];
        #pragma unroll
        for (int m = 0; m <= l; m++)     Pp[m]  = Pl[m];
    }

    if (full) {
        // hold the block (and its smem) until all bulk copies finished
        if (t == 0)
            asm volatile("cp.async.bulk.wait_group 0;" ::: "memory");
    } else {
        // tail / unaligned fallback (not hit for N = 2M)
        #pragma unroll
        for (int l = 1; l <= 7; l++) {
            const int w = 2 * l + 1;
            const float* src = smb + 128 * (l * l - 1);
            float* dst = out + (size_t)N * (size_t)(l * l)
                             + (size_t)bs * (size_t)w;
            const int cnt = rows * w;
            for (int i = t; i < cnt; i += TPB)
                dst[i] = src[i];
        }
    }
}

extern "C" void kernel_launch(void* const* d_in, const int* in_sizes, int n_in,
                              void* d_out, int out_size)
{
    const float* cos_theta = (const float*)d_in[0];
    const float* phi       = (const float*)d_in[1];
    float* out             = (float*)d_out;
    const int N = in_sizes[0];

    const int blocks = (N + TPB - 1) / TPB;
    sph_harm_kernel<<<blocks, TPB>>>(cos_theta, phi, out, N);
}